// round 16
// baseline (speedup 1.0000x reference)
#include <cuda_runtime.h>
#include <cuda_fp16.h>
#include <math.h>
#include <cstdint>

#define DIM   768
#define NH    12
#define HD    64
#define HID   3072
#define BATCH 4
#define SEQ   2048
#define NT    (BATCH*SEQ)
#define NBH   (BATCH*NH)
#define EXP2C 0.1803368801111245f   /* 0.125 * log2(e) */

typedef __half hf;

/* ---------------- scratch (device globals) ---------------- */
__device__ unsigned short g_h  [(size_t)NT * DIM];
__device__ unsigned short g_qkv[(size_t)NT * 3 * DIM];
__device__ unsigned short g_at [(size_t)NT * DIM];
__device__ float          g_x1 [(size_t)NT * DIM];
__device__ unsigned short g_h2 [(size_t)NT * DIM];
__device__ unsigned short g_ac [(size_t)NT * HID];
__device__ unsigned short g_wqkv[768*2304];
__device__ unsigned short g_wpr [768*768];
__device__ unsigned short g_w1  [768*3072];
__device__ unsigned short g_w2  [3072*768];
__device__ unsigned char  g_m8 [(size_t)BATCH * SEQ * SEQ];

/* ---------------- primitives ---------------- */
__device__ __forceinline__ uint32_t smem_u32(const void* p) {
    uint32_t a;
    asm("{ .reg .u64 t; cvta.to.shared.u64 t, %1; cvt.u32.u64 %0, t; }" : "=r"(a) : "l"(p));
    return a;
}
__device__ __forceinline__ void ldsm4(uint32_t* r, uint32_t a) {
    asm volatile("ldmatrix.sync.aligned.m8n8.x4.shared.b16 {%0,%1,%2,%3}, [%4];"
                 : "=r"(r[0]),"=r"(r[1]),"=r"(r[2]),"=r"(r[3]) : "r"(a));
}
__device__ __forceinline__ void ldsm2(uint32_t* r, uint32_t a) {
    asm volatile("ldmatrix.sync.aligned.m8n8.x2.shared.b16 {%0,%1}, [%2];"
                 : "=r"(r[0]),"=r"(r[1]) : "r"(a));
}
__device__ __forceinline__ void ldsm2t(uint32_t* r, uint32_t a) {
    asm volatile("ldmatrix.sync.aligned.m8n8.x2.trans.shared.b16 {%0,%1}, [%2];"
                 : "=r"(r[0]),"=r"(r[1]) : "r"(a));
}
__device__ __forceinline__ void mma_f16(float* d, const uint32_t* a, const uint32_t* b) {
    asm volatile("mma.sync.aligned.m16n8k16.row.col.f32.f16.f16.f32 "
                 "{%0,%1,%2,%3}, {%4,%5,%6,%7}, {%8,%9}, {%0,%1,%2,%3};"
                 : "+f"(d[0]),"+f"(d[1]),"+f"(d[2]),"+f"(d[3])
                 : "r"(a[0]),"r"(a[1]),"r"(a[2]),"r"(a[3]),"r"(b[0]),"r"(b[1]));
}
__device__ __forceinline__ void cpa16(uint32_t dst, const void* src) {
    asm volatile("cp.async.cg.shared.global [%0], [%1], 16;" :: "r"(dst), "l"(src));
}
#define CP_COMMIT() asm volatile("cp.async.commit_group;" ::: "memory")
#define CP_WAIT(n)  asm volatile("cp.async.wait_group %0;" :: "n"(n) : "memory")

/* smem layouts (validated): A tile [rows][32], swizzle c ^ ((r>>1)&3);
   B-trans tile [32][NTILE], swizzle c ^ (k&7) */
__device__ __forceinline__ int a_off(int r, int c) { return r * 64 + ((c ^ ((r >> 1) & 3)) << 4); }
template<int NTILE>
__device__ __forceinline__ int bt_off(int k, int c) { return k * (NTILE * 2) + ((c ^ (k & 7)) << 4); }

__device__ __forceinline__ void ld_atile1(uint32_t dh, const hf* gh, int stride, int tid)
{
    int row = tid >> 1, cp = (tid & 1) * 2;
    size_t o = (size_t)row * stride + cp * 8;
    cpa16(dh + a_off(row, cp),     gh + o);
    cpa16(dh + a_off(row, cp + 1), gh + o + 8);
}
template<int NTILE>
__device__ __forceinline__ void ld_bttile1(uint32_t dh, const hf* gh, int ldb, int tid)
{
    int k = tid >> 3, cb = tid & 7;
    size_t o = (size_t)k * ldb + cb * 8;
    cpa16(dh + bt_off<NTILE>(k, cb), gh + o);
    if (NTILE == 128)
        cpa16(dh + bt_off<NTILE>(k, cb + 8), gh + o + 64);
}

/* one BK=32 chunk, pure fp16: acc += A*B */
template<int MT>
__device__ __forceinline__ void mma_chunk1(
    uint32_t sA, uint32_t sB, int wm, int wn, int lane, float acc[][4][4])
{
    const int jA = lane >> 3, rA = lane & 7;
    const int jB = (lane >> 3) & 1, rB = lane & 7;
    #pragma unroll
    for (int ks = 0; ks < 32; ks += 16) {
        uint32_t A[MT][4], B[4][2];
        #pragma unroll
        for (int mt = 0; mt < MT; mt++) {
            int row = wm * MT * 16 + mt * 16 + (jA & 1) * 8 + rA;
            int cc  = (ks >> 3) + (jA >> 1);
            ldsm4(A[mt], sA + a_off(row, cc));
        }
        #pragma unroll
        for (int nt = 0; nt < 4; nt++) {
            int krow = ks + jB * 8 + rB;
            int cc   = (wn * 32 + nt * 8) >> 3;
            ldsm2t(B[nt], sB + bt_off<128>(krow, cc));
        }
        #pragma unroll
        for (int mt = 0; mt < MT; mt++)
            #pragma unroll
            for (int nt = 0; nt < 4; nt++)
                mma_f16(acc[mt][nt], A[mt], B[nt]);
    }
}

__device__ __forceinline__ uint32_t pack2h(float a, float b) {
    return (uint32_t)__half_as_ushort(__float2half_rn(a))
         | ((uint32_t)__half_as_ushort(__float2half_rn(b)) << 16);
}

/* ================= layernorm -> fp16 ================= */
__global__ __launch_bounds__(256) void ln_conv(
    const float* __restrict__ x, const float* __restrict__ gamma,
    const float* __restrict__ beta, hf* __restrict__ o)
{
    int row = blockIdx.x;
    const float* xr = x + (size_t)row * DIM;
    float s = 0.f, s2 = 0.f;
    for (int i = threadIdx.x; i < DIM; i += 256) { float v = xr[i]; s += v; s2 += v * v; }
    __shared__ float sh[64];
    #pragma unroll
    for (int off = 16; off > 0; off >>= 1) {
        s  += __shfl_xor_sync(0xffffffffu, s,  off);
        s2 += __shfl_xor_sync(0xffffffffu, s2, off);
    }
    int warp = threadIdx.x >> 5, lane = threadIdx.x & 31;
    if (lane == 0) { sh[warp] = s; sh[warp + 32] = s2; }
    __syncthreads();
    if (threadIdx.x < 32) {
        s  = (threadIdx.x < 8) ? sh[threadIdx.x]      : 0.f;
        s2 = (threadIdx.x < 8) ? sh[threadIdx.x + 32] : 0.f;
        #pragma unroll
        for (int off = 4; off > 0; off >>= 1) {
            s  += __shfl_xor_sync(0xffffffffu, s,  off);
            s2 += __shfl_xor_sync(0xffffffffu, s2, off);
        }
        if (lane == 0) { sh[0] = s; sh[1] = s2; }
    }
    __syncthreads();
    float mu  = sh[0] * (1.f / DIM);
    float inv = rsqrtf(sh[1] * (1.f / DIM) - mu * mu + 1e-6f);
    for (int i = threadIdx.x; i < DIM; i += 256) {
        float v = (xr[i] - mu) * inv * gamma[i] + beta[i];
        o[(size_t)row * DIM + i] = __float2half_rn(v);
    }
}

/* ================= weight convert ================= */
__global__ __launch_bounds__(256) void wconv(
    const float* __restrict__ src, hf* __restrict__ dst, int n)
{
    int i = (blockIdx.x * 256 + threadIdx.x) * 4;
    if (i >= n) return;
    float4 v = *(const float4*)(src + i);
    uint2 o; o.x = pack2h(v.x, v.y); o.y = pack2h(v.z, v.w);
    *(uint2*)(dst + i) = o;
}

/* ================= mask int32 -> uint8 ================= */
__global__ __launch_bounds__(256) void mconv(
    const int* __restrict__ src, unsigned char* __restrict__ dst, int n)
{
    int i = (blockIdx.x * 256 + threadIdx.x) * 16;
    if (i >= n) return;
    uint32_t p[4];
    #pragma unroll
    for (int g = 0; g < 4; g++) {
        int4 a = *(const int4*)(src + i + g * 4);
        p[g] = (uint32_t)(a.x != 0) | ((uint32_t)(a.y != 0) << 8)
             | ((uint32_t)(a.z != 0) << 16) | ((uint32_t)(a.w != 0) << 24);
    }
    uint4 o; o.x = p[0]; o.y = p[1]; o.z = p[2]; o.w = p[3];
    *(uint4*)(dst + i) = o;
}

/* ================= fused flash attention (pure fp16, max-free softmax) ====== */
__global__ __launch_bounds__(256, 2) void flash_attn(
    const hf* __restrict__ qkv, const unsigned char* __restrict__ m8,
    hf* __restrict__ attn)
{
    extern __shared__ __align__(1024) char smx[];
    uint32_t sb = smem_u32(smx);
    const int tid = threadIdx.x, lane = tid & 31, w = tid >> 5;
    const int z = blockIdx.y, b = z / NH, h = z % NH;
    const int m0 = blockIdx.x * 128;
    const int jA = lane >> 3, rA = lane & 7;
    const int jB = (lane >> 3) & 1, rB = lane & 7;

    /* stage Q (128x64), pull into registers */
    {
        const hf* Qg = qkv + (size_t)(b * SEQ + m0) * 2304 + h * 64;
        int row = tid >> 1, cp = (tid & 1) * 2;
        size_t o = (size_t)row * 2304 + cp * 8;
        cpa16(sb +        a_off(row, cp),     Qg + o);
        cpa16(sb +        a_off(row, cp + 1), Qg + o + 8);
        cpa16(sb + 8192 + a_off(row, cp),     Qg + o + 32);
        cpa16(sb + 8192 + a_off(row, cp + 1), Qg + o + 40);
        CP_COMMIT(); CP_WAIT(0);
    }
    __syncthreads();
    uint32_t qf[4][4];
    #pragma unroll
    for (int ks = 0; ks < 4; ks++) {
        int off = (ks >> 1) * 8192 + a_off(w * 16 + (jA & 1) * 8 + rA, ((ks & 1) << 1) + (jA >> 1));
        ldsm4(qf[ks], sb + off);
    }
    __syncthreads();

    const int kr_row = tid >> 2, kc4 = tid & 3;
    const int vr = tid >> 3, vcb = tid & 7;
    auto issue_kv = [&](int kt, int s) {
        uint32_t base = sb + s * 16384;
        const hf* Kg = qkv + (size_t)(b * SEQ + kt * 64 + kr_row) * 2304 + 768 + h * 64;
        cpa16(base +    0 + a_off(kr_row, kc4), Kg + kc4 * 8);
        cpa16(base + 4096 + a_off(kr_row, kc4), Kg + 32 + kc4 * 8);
        const hf* Vg = qkv + (size_t)(b * SEQ + kt * 64 + vr) * 2304 + 1536 + h * 64 + vcb * 8;
        cpa16(base +  8192 + bt_off<64>(vr, vcb), Vg);
        cpa16(base + 12288 + bt_off<64>(vr, vcb), Vg + 32 * 2304);
        CP_COMMIT();
    };

    float oacc[8][4] = {};
    float l_a = 0.f, l_b = 0.f;
    const unsigned char* mrow_a = m8 + (size_t)b * SEQ * SEQ
                                + (size_t)(m0 + w * 16 + (lane >> 2)) * SEQ + (lane & 3) * 2;
    const unsigned char* mrow_b = mrow_a + 8 * SEQ;
    const int nkt = SEQ / 64;

    issue_kv(0, 0);
    issue_kv(1, 1);
    for (int kt = 0; kt < nkt; kt++) {
        if (kt + 1 < nkt) { CP_WAIT(1); } else { CP_WAIT(0); }
        __syncthreads();
        if (kt + 2 < nkt) issue_kv(kt + 2, (kt + 2) % 3);
        uint32_t st = sb + (kt % 3) * 16384;

        /* S = Q K^T */
        float sacc[8][4] = {};
        #pragma unroll
        for (int ks = 0; ks < 4; ks++) {
            int cbase = (ks >> 1) * 4096;
            int cc = ((ks & 1) << 1) + jB;
            uint32_t Bf[8][2];
            #pragma unroll
            for (int nt = 0; nt < 8; nt++)
                ldsm2(Bf[nt], st + cbase + a_off(nt * 8 + rB, cc));
            #pragma unroll
            for (int nt = 0; nt < 8; nt++) mma_f16(sacc[nt], qf[ks], Bf[nt]);
        }

        /* max-free softmax: p = mask ? 2^(S*scale*log2e) : 0 */
        #pragma unroll
        for (int nt = 0; nt < 8; nt++) {
            uchar2 ma = *(const uchar2*)(mrow_a + kt * 64 + nt * 8);
            uchar2 mb = *(const uchar2*)(mrow_b + kt * 64 + nt * 8);
            sacc[nt][0] = ma.x ? exp2f(sacc[nt][0] * EXP2C) : 0.f;
            sacc[nt][1] = ma.y ? exp2f(sacc[nt][1] * EXP2C) : 0.f;
            sacc[nt][2] = mb.x ? exp2f(sacc[nt][2] * EXP2C) : 0.f;
            sacc[nt][3] = mb.y ? exp2f(sacc[nt][3] * EXP2C) : 0.f;
            l_a += sacc[nt][0] + sacc[nt][1];
            l_b += sacc[nt][2] + sacc[nt][3];
        }

        /* O += P V */
        #pragma unroll
        for (int ks = 0; ks < 4; ks++) {
            uint32_t pf[4];
            pf[0] = pack2h(sacc[2*ks  ][0], sacc[2*ks  ][1]);
            pf[1] = pack2h(sacc[2*ks  ][2], sacc[2*ks  ][3]);
            pf[2] = pack2h(sacc[2*ks+1][0], sacc[2*ks+1][1]);
            pf[3] = pack2h(sacc[2*ks+1][2], sacc[2*ks+1][3]);
            int cbase = (ks >> 1) * 4096;
            int krow = (ks & 1) * 16 + jB * 8 + rB;
            uint32_t Vf[8][2];
            #pragma unroll
            for (int nt = 0; nt < 8; nt++)
                ldsm2t(Vf[nt], st + 8192 + cbase + bt_off<64>(krow, nt));
            #pragma unroll
            for (int nt = 0; nt < 8; nt++) mma_f16(oacc[nt], pf, Vf[nt]);
        }
    }

    /* reduce l across the quad (lanes differing in bits 0-1) */
    l_a += __shfl_xor_sync(0xffffffffu, l_a, 1);
    l_a += __shfl_xor_sync(0xffffffffu, l_a, 2);
    l_b += __shfl_xor_sync(0xffffffffu, l_b, 1);
    l_b += __shfl_xor_sync(0xffffffffu, l_b, 2);
    float inv_a = 1.f / l_a, inv_b = 1.f / l_b;
    #pragma unroll
    for (int nt = 0; nt < 8; nt++) {
        int col = h * 64 + nt * 8 + (lane & 3) * 2;
        size_t off = (size_t)(b * SEQ + m0 + w * 16 + (lane >> 2)) * DIM + col;
        *(uint32_t*)(attn + off)           = pack2h(oacc[nt][0] * inv_a, oacc[nt][1] * inv_a);
        *(uint32_t*)(attn + off + 8 * DIM) = pack2h(oacc[nt][2] * inv_b, oacc[nt][3] * inv_b);
    }
}

/* ================= linear GEMM (pure fp16, cp.async 3-stage, 2 CTA/SM) ======= */
template<bool GELU, bool RESID, bool HALFOUT>
__global__ __launch_bounds__(256, 2) void lin_gemm(
    const hf* __restrict__ A, int lda,
    const hf* __restrict__ W, int ldb,
    const float* __restrict__ bias, const float* __restrict__ resid,
    float* __restrict__ outf, hf* __restrict__ outh,
    int ldc, int K)
{
    extern __shared__ __align__(1024) char smx[];
    uint32_t sb = smem_u32(smx);
    const int tid = threadIdx.x, lane = tid & 31, wid = tid >> 5;
    const int wm = wid >> 2, wn = wid & 3;
    const int m0 = blockIdx.y * 128, n0 = blockIdx.x * 128;
    float acc[4][4][4] = {};
    const int nch = K >> 5;

    auto issue = [&](int c, int s) {
        uint32_t base = sb + s * 16384;
        ld_atile1(base, A + (size_t)m0 * lda + c * 32, lda, tid);
        ld_bttile1<128>(base + 8192, W + (size_t)(c * 32) * ldb + n0, ldb, tid);
        CP_COMMIT();
    };

    issue(0, 0);
    issue(1, 1);
    for (int c = 0; c < nch; c++) {
        if (c + 1 < nch) { CP_WAIT(1); } else { CP_WAIT(0); }
        __syncthreads();
        if (c + 2 < nch) issue(c + 2, (c + 2) % 3);
        uint32_t st = sb + (c % 3) * 16384;
        mma_chunk1<4>(st, st + 8192, wm, wn, lane, acc);
    }

    #pragma unroll
    for (int mt = 0; mt < 4; mt++)
        #pragma unroll
        for (int nt = 0; nt < 4; nt++) {
            int n = n0 + wn * 32 + nt * 8 + (lane & 3) * 2;
            float bx = __ldg(bias + n), by = __ldg(bias + n + 1);
            #pragma unroll
            for (int hfx = 0; hfx < 2; hfx++) {
                int m = m0 + wm * 64 + mt * 16 + (lane >> 2) + hfx * 8;
                float v0 = acc[mt][nt][hfx * 2]     + bx;
                float v1 = acc[mt][nt][hfx * 2 + 1] + by;
                if (GELU) {
                    v0 = 0.5f * v0 * (1.f + erff(v0 * 0.7071067811865476f));
                    v1 = 0.5f * v1 * (1.f + erff(v1 * 0.7071067811865476f));
                }
                size_t off = (size_t)m * ldc + n;
                if (HALFOUT) {
                    *(uint32_t*)(outh + off) = pack2h(v0, v1);
                } else {
                    if (RESID) {
                        float2 r = *(const float2*)(resid + off);
                        v0 += r.x; v1 += r.y;
                    }
                    float2 o2; o2.x = v0; o2.y = v1;
                    *(float2*)(outf + off) = o2;
                }
            }
        }
}

/* ================= driver ================= */
extern "C" void kernel_launch(void* const* d_in, const int* in_sizes, int n_in,
                              void* d_out, int out_size)
{
    const float* x      = (const float*)d_in[0];
    const int*   mask   = (const int*)  d_in[1];
    const float* w_qkv  = (const float*)d_in[2];
    const float* b_qkv  = (const float*)d_in[3];
    const float* w_proj = (const float*)d_in[4];
    const float* b_proj = (const float*)d_in[5];
    const float* g1     = (const float*)d_in[6];
    const float* beta1  = (const float*)d_in[7];
    const float* g2     = (const float*)d_in[8];
    const float* beta2  = (const float*)d_in[9];
    const float* w1     = (const float*)d_in[10];
    const float* b1     = (const float*)d_in[11];
    const float* w2     = (const float*)d_in[12];
    const float* b2     = (const float*)d_in[13];
    float* out = (float*)d_out;

    hf *hh, *qk, *at, *h2, *ac, *wq, *wp, *wf1, *wf2;
    float *x1;
    unsigned char* m8;
    cudaGetSymbolAddress((void**)&hh,  g_h);
    cudaGetSymbolAddress((void**)&qk,  g_qkv);
    cudaGetSymbolAddress((void**)&at,  g_at);
    cudaGetSymbolAddress((void**)&x1,  g_x1);
    cudaGetSymbolAddress((void**)&h2,  g_h2);
    cudaGetSymbolAddress((void**)&ac,  g_ac);
    cudaGetSymbolAddress((void**)&wq,  g_wqkv);
    cudaGetSymbolAddress((void**)&wp,  g_wpr);
    cudaGetSymbolAddress((void**)&wf1, g_w1);
    cudaGetSymbolAddress((void**)&wf2, g_w2);
    cudaGetSymbolAddress((void**)&m8,  g_m8);

    cudaFuncSetAttribute(lin_gemm<false,false,true>,  cudaFuncAttributeMaxDynamicSharedMemorySize, 49152);
    cudaFuncSetAttribute(lin_gemm<false,true,false>,  cudaFuncAttributeMaxDynamicSharedMemorySize, 49152);
    cudaFuncSetAttribute(lin_gemm<true,false,true>,   cudaFuncAttributeMaxDynamicSharedMemorySize, 49152);
    cudaFuncSetAttribute(flash_attn,                  cudaFuncAttributeMaxDynamicSharedMemorySize, 49152);

    wconv<<<1728, 256>>>(w_qkv,  wq,  768 * 2304);
    wconv<<<576,  256>>>(w_proj, wp,  768 * 768);
    wconv<<<2304, 256>>>(w1,     wf1, 768 * 3072);
    wconv<<<2304, 256>>>(w2,     wf2, 3072 * 768);
    mconv<<<4096, 256>>>(mask, m8, BATCH * SEQ * SEQ);

    ln_conv<<<NT, 256>>>(x, g1, beta1, hh);
    lin_gemm<false, false, true><<<dim3(18, 64), 256, 49152>>>(
        hh, DIM, wq, 3 * DIM, b_qkv, nullptr,
        nullptr, qk, 3 * DIM, DIM);
    flash_attn<<<dim3(16, NBH), 256, 49152>>>(qk, m8, at);
    lin_gemm<false, true, false><<<dim3(6, 64), 256, 49152>>>(
        at, DIM, wp, DIM, b_proj, x,
        x1, nullptr, DIM, DIM);
    ln_conv<<<NT, 256>>>(x1, g2, beta2, h2);
    lin_gemm<true, false, true><<<dim3(24, 64), 256, 49152>>>(
        h2, DIM, wf1, HID, b1, nullptr,
        nullptr, ac, HID, DIM);
    lin_gemm<false, true, false><<<dim3(6, 64), 256, 49152>>>(
        ac, HID, wf2, DIM, b2, x1,
        out, nullptr, DIM, HID);
}

// round 17
// speedup vs baseline: 1.0465x; 1.0465x over previous
#include <cuda_runtime.h>
#include <cuda_fp16.h>
#include <math.h>
#include <cstdint>

#define DIM   768
#define NH    12
#define HD    64
#define HID   3072
#define BATCH 4
#define SEQ   2048
#define NT    (BATCH*SEQ)
#define NBH   (BATCH*NH)
#define ATTN_SCALE 0.125f

typedef __half hf;

/* ---------------- scratch (device globals) ---------------- */
__device__ unsigned short g_h  [(size_t)NT * DIM];
__device__ unsigned short g_qkv[(size_t)NT * 3 * DIM];
__device__ unsigned short g_at [(size_t)NT * DIM];
__device__ float          g_x1 [(size_t)NT * DIM];
__device__ unsigned short g_h2 [(size_t)NT * DIM];
__device__ unsigned short g_ac [(size_t)NT * HID];
__device__ unsigned short g_wqkv[768*2304];
__device__ unsigned short g_wpr [768*768];
__device__ unsigned short g_w1  [768*3072];
__device__ unsigned short g_w2  [3072*768];

/* ---------------- primitives ---------------- */
__device__ __forceinline__ uint32_t smem_u32(const void* p) {
    uint32_t a;
    asm("{ .reg .u64 t; cvta.to.shared.u64 t, %1; cvt.u32.u64 %0, t; }" : "=r"(a) : "l"(p));
    return a;
}
__device__ __forceinline__ void ldsm4(uint32_t* r, uint32_t a) {
    asm volatile("ldmatrix.sync.aligned.m8n8.x4.shared.b16 {%0,%1,%2,%3}, [%4];"
                 : "=r"(r[0]),"=r"(r[1]),"=r"(r[2]),"=r"(r[3]) : "r"(a));
}
__device__ __forceinline__ void ldsm2(uint32_t* r, uint32_t a) {
    asm volatile("ldmatrix.sync.aligned.m8n8.x2.shared.b16 {%0,%1}, [%2];"
                 : "=r"(r[0]),"=r"(r[1]) : "r"(a));
}
__device__ __forceinline__ void ldsm2t(uint32_t* r, uint32_t a) {
    asm volatile("ldmatrix.sync.aligned.m8n8.x2.trans.shared.b16 {%0,%1}, [%2];"
                 : "=r"(r[0]),"=r"(r[1]) : "r"(a));
}
__device__ __forceinline__ void mma_f16(float* d, const uint32_t* a, const uint32_t* b) {
    asm volatile("mma.sync.aligned.m16n8k16.row.col.f32.f16.f16.f32 "
                 "{%0,%1,%2,%3}, {%4,%5,%6,%7}, {%8,%9}, {%0,%1,%2,%3};"
                 : "+f"(d[0]),"+f"(d[1]),"+f"(d[2]),"+f"(d[3])
                 : "r"(a[0]),"r"(a[1]),"r"(a[2]),"r"(a[3]),"r"(b[0]),"r"(b[1]));
}
__device__ __forceinline__ void cpa16(uint32_t dst, const void* src) {
    asm volatile("cp.async.cg.shared.global [%0], [%1], 16;" :: "r"(dst), "l"(src));
}
#define CP_COMMIT() asm volatile("cp.async.commit_group;" ::: "memory")
#define CP_WAIT(n)  asm volatile("cp.async.wait_group %0;" :: "n"(n) : "memory")

/* smem layouts (validated): A tile [rows][32], swizzle c ^ ((r>>1)&3);
   B-trans tile [32][NTILE], swizzle c ^ (k&7) */
__device__ __forceinline__ int a_off(int r, int c) { return r * 64 + ((c ^ ((r >> 1) & 3)) << 4); }
template<int NTILE>
__device__ __forceinline__ int bt_off(int k, int c) { return k * (NTILE * 2) + ((c ^ (k & 7)) << 4); }

__device__ __forceinline__ void ld_atile1(uint32_t dh, const hf* gh, int stride, int tid)
{
    int row = tid >> 1, cp = (tid & 1) * 2;
    size_t o = (size_t)row * stride + cp * 8;
    cpa16(dh + a_off(row, cp),     gh + o);
    cpa16(dh + a_off(row, cp + 1), gh + o + 8);
}
template<int NTILE>
__device__ __forceinline__ void ld_bttile1(uint32_t dh, const hf* gh, int ldb, int tid)
{
    int k = tid >> 3, cb = tid & 7;
    size_t o = (size_t)k * ldb + cb * 8;
    cpa16(dh + bt_off<NTILE>(k, cb), gh + o);
    if (NTILE == 128)
        cpa16(dh + bt_off<NTILE>(k, cb + 8), gh + o + 64);
}

/* one BK=32 sub-chunk, pure fp16: acc += A*B */
template<int MT>
__device__ __forceinline__ void mma_chunk1(
    uint32_t sA, uint32_t sB, int wm, int wn, int lane, float acc[][4][4])
{
    const int jA = lane >> 3, rA = lane & 7;
    const int jB = (lane >> 3) & 1, rB = lane & 7;
    #pragma unroll
    for (int ks = 0; ks < 32; ks += 16) {
        uint32_t A[MT][4], B[4][2];
        #pragma unroll
        for (int mt = 0; mt < MT; mt++) {
            int row = wm * MT * 16 + mt * 16 + (jA & 1) * 8 + rA;
            int cc  = (ks >> 3) + (jA >> 1);
            ldsm4(A[mt], sA + a_off(row, cc));
        }
        #pragma unroll
        for (int nt = 0; nt < 4; nt++) {
            int krow = ks + jB * 8 + rB;
            int cc   = (wn * 32 + nt * 8) >> 3;
            ldsm2t(B[nt], sB + bt_off<128>(krow, cc));
        }
        #pragma unroll
        for (int mt = 0; mt < MT; mt++)
            #pragma unroll
            for (int nt = 0; nt < 4; nt++)
                mma_f16(acc[mt][nt], A[mt], B[nt]);
    }
}

__device__ __forceinline__ uint32_t pack2h(float a, float b) {
    return (uint32_t)__half_as_ushort(__float2half_rn(a))
         | ((uint32_t)__half_as_ushort(__float2half_rn(b)) << 16);
}

/* ================= layernorm -> fp16 ================= */
__global__ __launch_bounds__(256) void ln_conv(
    const float* __restrict__ x, const float* __restrict__ gamma,
    const float* __restrict__ beta, hf* __restrict__ o)
{
    int row = blockIdx.x;
    const float* xr = x + (size_t)row * DIM;
    float s = 0.f, s2 = 0.f;
    for (int i = threadIdx.x; i < DIM; i += 256) { float v = xr[i]; s += v; s2 += v * v; }
    __shared__ float sh[64];
    #pragma unroll
    for (int off = 16; off > 0; off >>= 1) {
        s  += __shfl_xor_sync(0xffffffffu, s,  off);
        s2 += __shfl_xor_sync(0xffffffffu, s2, off);
    }
    int warp = threadIdx.x >> 5, lane = threadIdx.x & 31;
    if (lane == 0) { sh[warp] = s; sh[warp + 32] = s2; }
    __syncthreads();
    if (threadIdx.x < 32) {
        s  = (threadIdx.x < 8) ? sh[threadIdx.x]      : 0.f;
        s2 = (threadIdx.x < 8) ? sh[threadIdx.x + 32] : 0.f;
        #pragma unroll
        for (int off = 4; off > 0; off >>= 1) {
            s  += __shfl_xor_sync(0xffffffffu, s,  off);
            s2 += __shfl_xor_sync(0xffffffffu, s2, off);
        }
        if (lane == 0) { sh[0] = s; sh[1] = s2; }
    }
    __syncthreads();
    float mu  = sh[0] * (1.f / DIM);
    float inv = rsqrtf(sh[1] * (1.f / DIM) - mu * mu + 1e-6f);
    for (int i = threadIdx.x; i < DIM; i += 256) {
        float v = (xr[i] - mu) * inv * gamma[i] + beta[i];
        o[(size_t)row * DIM + i] = __float2half_rn(v);
    }
}

/* ================= weight convert ================= */
__global__ __launch_bounds__(256) void wconv(
    const float* __restrict__ src, hf* __restrict__ dst, int n)
{
    int i = (blockIdx.x * 256 + threadIdx.x) * 4;
    if (i >= n) return;
    float4 v = *(const float4*)(src + i);
    uint2 o; o.x = pack2h(v.x, v.y); o.y = pack2h(v.z, v.w);
    *(uint2*)(dst + i) = o;
}

/* ================= fused flash attention (pure fp16, 2 CTA/SM) ========== */
__global__ __launch_bounds__(256, 2) void flash_attn(
    const hf* __restrict__ qkv, const int* __restrict__ mask,
    hf* __restrict__ attn)
{
    extern __shared__ __align__(1024) char smx[];
    uint32_t sb = smem_u32(smx);
    const int tid = threadIdx.x, lane = tid & 31, w = tid >> 5;
    const int z = blockIdx.y, b = z / NH, h = z % NH;
    const int m0 = blockIdx.x * 128;
    const int jA = lane >> 3, rA = lane & 7;
    const int jB = (lane >> 3) & 1, rB = lane & 7;

    /* stage Q (128x64) in first 16KB, pull into registers */
    {
        const hf* Qg = qkv + (size_t)(b * SEQ + m0) * 2304 + h * 64;
        int row = tid >> 1, cp = (tid & 1) * 2;
        size_t o = (size_t)row * 2304 + cp * 8;
        cpa16(sb +        a_off(row, cp),     Qg + o);
        cpa16(sb +        a_off(row, cp + 1), Qg + o + 8);
        cpa16(sb + 8192 + a_off(row, cp),     Qg + o + 32);
        cpa16(sb + 8192 + a_off(row, cp + 1), Qg + o + 40);
        CP_COMMIT(); CP_WAIT(0);
    }
    __syncthreads();
    uint32_t qf[4][4];
    #pragma unroll
    for (int ks = 0; ks < 4; ks++) {
        int off = (ks >> 1) * 8192 + a_off(w * 16 + (jA & 1) * 8 + rA, ((ks & 1) << 1) + (jA >> 1));
        ldsm4(qf[ks], sb + off);
    }
    __syncthreads();

    const int kr_row = tid >> 2, kc4 = tid & 3;
    const int vr = tid >> 3, vcb = tid & 7;
    auto issue_kv = [&](int kt, int s) {
        uint32_t base = sb + s * 16384;
        const hf* Kg = qkv + (size_t)(b * SEQ + kt * 64 + kr_row) * 2304 + 768 + h * 64;
        cpa16(base +    0 + a_off(kr_row, kc4), Kg + kc4 * 8);
        cpa16(base + 4096 + a_off(kr_row, kc4), Kg + 32 + kc4 * 8);
        const hf* Vg = qkv + (size_t)(b * SEQ + kt * 64 + vr) * 2304 + 1536 + h * 64 + vcb * 8;
        cpa16(base +  8192 + bt_off<64>(vr, vcb), Vg);
        cpa16(base + 12288 + bt_off<64>(vr, vcb), Vg + 32 * 2304);
        CP_COMMIT();
    };

    float oacc[8][4] = {};
    float m_a = -1e30f, m_b = -1e30f, l_a = 0.f, l_b = 0.f;
    const int* mrow_a = mask + (size_t)b * SEQ * SEQ + (size_t)(m0 + w * 16 + (lane >> 2)) * SEQ;
    const int* mrow_b = mrow_a + 8 * SEQ;
    const int nkt = SEQ / 64;

    issue_kv(0, 0);
    issue_kv(1, 1);
    for (int kt = 0; kt < nkt; kt++) {
        if (kt + 1 < nkt) { CP_WAIT(1); } else { CP_WAIT(0); }
        __syncthreads();
        if (kt + 2 < nkt) issue_kv(kt + 2, (kt + 2) % 3);
        uint32_t st = sb + (kt % 3) * 16384;

        /* S = Q K^T (pure fp16) */
        float sacc[8][4] = {};
        #pragma unroll
        for (int ks = 0; ks < 4; ks++) {
            int cbase = (ks >> 1) * 4096;
            int cc = ((ks & 1) << 1) + jB;
            uint32_t Bf[8][2];
            #pragma unroll
            for (int nt = 0; nt < 8; nt++)
                ldsm2(Bf[nt], st + cbase + a_off(nt * 8 + rB, cc));
            #pragma unroll
            for (int nt = 0; nt < 8; nt++) mma_f16(sacc[nt], qf[ks], Bf[nt]);
        }

        /* mask + scale + online softmax */
        const int* mka = mrow_a + kt * 64 + (lane & 3) * 2;
        const int* mkb = mrow_b + kt * 64 + (lane & 3) * 2;
        float mx_a = -1e30f, mx_b = -1e30f;
        #pragma unroll
        for (int nt = 0; nt < 8; nt++) {
            int2 ma = *(const int2*)(mka + nt * 8);
            int2 mb = *(const int2*)(mkb + nt * 8);
            sacc[nt][0] = ma.x ? sacc[nt][0] * ATTN_SCALE : -10000.f;
            sacc[nt][1] = ma.y ? sacc[nt][1] * ATTN_SCALE : -10000.f;
            sacc[nt][2] = mb.x ? sacc[nt][2] * ATTN_SCALE : -10000.f;
            sacc[nt][3] = mb.y ? sacc[nt][3] * ATTN_SCALE : -10000.f;
            mx_a = fmaxf(mx_a, fmaxf(sacc[nt][0], sacc[nt][1]));
            mx_b = fmaxf(mx_b, fmaxf(sacc[nt][2], sacc[nt][3]));
        }
        mx_a = fmaxf(mx_a, __shfl_xor_sync(0xffffffffu, mx_a, 1));
        mx_a = fmaxf(mx_a, __shfl_xor_sync(0xffffffffu, mx_a, 2));
        mx_b = fmaxf(mx_b, __shfl_xor_sync(0xffffffffu, mx_b, 1));
        mx_b = fmaxf(mx_b, __shfl_xor_sync(0xffffffffu, mx_b, 2));
        float mn_a = fmaxf(m_a, mx_a), mn_b = fmaxf(m_b, mx_b);
        float al_a = __expf(m_a - mn_a), al_b = __expf(m_b - mn_b);
        m_a = mn_a; m_b = mn_b;
        float s_a = 0.f, s_b = 0.f;
        #pragma unroll
        for (int nt = 0; nt < 8; nt++) {
            sacc[nt][0] = __expf(sacc[nt][0] - mn_a);
            sacc[nt][1] = __expf(sacc[nt][1] - mn_a);
            sacc[nt][2] = __expf(sacc[nt][2] - mn_b);
            sacc[nt][3] = __expf(sacc[nt][3] - mn_b);
            s_a += sacc[nt][0] + sacc[nt][1];
            s_b += sacc[nt][2] + sacc[nt][3];
        }
        s_a += __shfl_xor_sync(0xffffffffu, s_a, 1);
        s_a += __shfl_xor_sync(0xffffffffu, s_a, 2);
        s_b += __shfl_xor_sync(0xffffffffu, s_b, 1);
        s_b += __shfl_xor_sync(0xffffffffu, s_b, 2);
        l_a = al_a * l_a + s_a;
        l_b = al_b * l_b + s_b;
        #pragma unroll
        for (int nt = 0; nt < 8; nt++) {
            oacc[nt][0] *= al_a; oacc[nt][1] *= al_a;
            oacc[nt][2] *= al_b; oacc[nt][3] *= al_b;
        }

        /* O += P V (P plain fp16) */
        #pragma unroll
        for (int ks = 0; ks < 4; ks++) {
            uint32_t pf[4];
            pf[0] = pack2h(sacc[2*ks  ][0], sacc[2*ks  ][1]);
            pf[1] = pack2h(sacc[2*ks  ][2], sacc[2*ks  ][3]);
            pf[2] = pack2h(sacc[2*ks+1][0], sacc[2*ks+1][1]);
            pf[3] = pack2h(sacc[2*ks+1][2], sacc[2*ks+1][3]);
            int cbase = (ks >> 1) * 4096;
            int krow = (ks & 1) * 16 + jB * 8 + rB;
            uint32_t Vf[8][2];
            #pragma unroll
            for (int nt = 0; nt < 8; nt++)
                ldsm2t(Vf[nt], st + 8192 + cbase + bt_off<64>(krow, nt));
            #pragma unroll
            for (int nt = 0; nt < 8; nt++) mma_f16(oacc[nt], pf, Vf[nt]);
        }
    }

    float inv_a = 1.f / l_a, inv_b = 1.f / l_b;
    #pragma unroll
    for (int nt = 0; nt < 8; nt++) {
        int col = h * 64 + nt * 8 + (lane & 3) * 2;
        size_t off = (size_t)(b * SEQ + m0 + w * 16 + (lane >> 2)) * DIM + col;
        *(uint32_t*)(attn + off)           = pack2h(oacc[nt][0] * inv_a, oacc[nt][1] * inv_a);
        *(uint32_t*)(attn + off + 8 * DIM) = pack2h(oacc[nt][2] * inv_b, oacc[nt][3] * inv_b);
    }
}

/* ================= linear GEMM (pure fp16, BK=64, cp.async 3-stage, 2 CTA/SM) == */
template<bool GELU, bool RESID, bool HALFOUT>
__global__ __launch_bounds__(256, 2) void lin_gemm(
    const hf* __restrict__ A, int lda,
    const hf* __restrict__ W, int ldb,
    const float* __restrict__ bias, const float* __restrict__ resid,
    float* __restrict__ outf, hf* __restrict__ outh,
    int ldc, int K)
{
    extern __shared__ __align__(1024) char smx[];
    uint32_t sb = smem_u32(smx);
    const int tid = threadIdx.x, lane = tid & 31, wid = tid >> 5;
    const int wm = wid >> 2, wn = wid & 3;
    const int m0 = blockIdx.y * 128, n0 = blockIdx.x * 128;
    float acc[4][4][4] = {};
    const int nch = K >> 6;   /* BK=64 */

    /* stage 32KB: A(k lo 32) 8K | A(k hi 32) 8K | B(k lo 32) 8K | B(k hi 32) 8K */
    auto issue = [&](int c, int s) {
        uint32_t base = sb + s * 32768;
        const hf* Ab = A + (size_t)m0 * lda + c * 64;
        ld_atile1(base,        Ab,      lda, tid);
        ld_atile1(base + 8192, Ab + 32, lda, tid);
        const hf* Wb = W + (size_t)(c * 64) * ldb + n0;
        ld_bttile1<128>(base + 16384, Wb,                    ldb, tid);
        ld_bttile1<128>(base + 24576, Wb + (size_t)32 * ldb, ldb, tid);
        CP_COMMIT();
    };

    issue(0, 0);
    issue(1, 1);
    for (int c = 0; c < nch; c++) {
        if (c + 1 < nch) { CP_WAIT(1); } else { CP_WAIT(0); }
        __syncthreads();
        if (c + 2 < nch) issue(c + 2, (c + 2) % 3);
        uint32_t st = sb + (c % 3) * 32768;
        mma_chunk1<4>(st,        st + 16384, wm, wn, lane, acc);
        mma_chunk1<4>(st + 8192, st + 24576, wm, wn, lane, acc);
    }

    #pragma unroll
    for (int mt = 0; mt < 4; mt++)
        #pragma unroll
        for (int nt = 0; nt < 4; nt++) {
            int n = n0 + wn * 32 + nt * 8 + (lane & 3) * 2;
            float bx = __ldg(bias + n), by = __ldg(bias + n + 1);
            #pragma unroll
            for (int hfx = 0; hfx < 2; hfx++) {
                int m = m0 + wm * 64 + mt * 16 + (lane >> 2) + hfx * 8;
                float v0 = acc[mt][nt][hfx * 2]     + bx;
                float v1 = acc[mt][nt][hfx * 2 + 1] + by;
                if (GELU) {
                    v0 = 0.5f * v0 * (1.f + erff(v0 * 0.7071067811865476f));
                    v1 = 0.5f * v1 * (1.f + erff(v1 * 0.7071067811865476f));
                }
                size_t off = (size_t)m * ldc + n;
                if (HALFOUT) {
                    *(uint32_t*)(outh + off) = pack2h(v0, v1);
                } else {
                    if (RESID) {
                        float2 r = *(const float2*)(resid + off);
                        v0 += r.x; v1 += r.y;
                    }
                    float2 o2; o2.x = v0; o2.y = v1;
                    *(float2*)(outf + off) = o2;
                }
            }
        }
}

/* ================= driver ================= */
extern "C" void kernel_launch(void* const* d_in, const int* in_sizes, int n_in,
                              void* d_out, int out_size)
{
    const float* x      = (const float*)d_in[0];
    const int*   mask   = (const int*)  d_in[1];
    const float* w_qkv  = (const float*)d_in[2];
    const float* b_qkv  = (const float*)d_in[3];
    const float* w_proj = (const float*)d_in[4];
    const float* b_proj = (const float*)d_in[5];
    const float* g1     = (const float*)d_in[6];
    const float* beta1  = (const float*)d_in[7];
    const float* g2     = (const float*)d_in[8];
    const float* beta2  = (const float*)d_in[9];
    const float* w1     = (const float*)d_in[10];
    const float* b1     = (const float*)d_in[11];
    const float* w2     = (const float*)d_in[12];
    const float* b2     = (const float*)d_in[13];
    float* out = (float*)d_out;

    hf *hh, *qk, *at, *h2, *ac, *wq, *wp, *wf1, *wf2;
    float *x1;
    cudaGetSymbolAddress((void**)&hh,  g_h);
    cudaGetSymbolAddress((void**)&qk,  g_qkv);
    cudaGetSymbolAddress((void**)&at,  g_at);
    cudaGetSymbolAddress((void**)&x1,  g_x1);
    cudaGetSymbolAddress((void**)&h2,  g_h2);
    cudaGetSymbolAddress((void**)&ac,  g_ac);
    cudaGetSymbolAddress((void**)&wq,  g_wqkv);
    cudaGetSymbolAddress((void**)&wp,  g_wpr);
    cudaGetSymbolAddress((void**)&wf1, g_w1);
    cudaGetSymbolAddress((void**)&wf2, g_w2);

    cudaFuncSetAttribute(lin_gemm<false,false,true>,  cudaFuncAttributeMaxDynamicSharedMemorySize, 98304);
    cudaFuncSetAttribute(lin_gemm<false,true,false>,  cudaFuncAttributeMaxDynamicSharedMemorySize, 98304);
    cudaFuncSetAttribute(lin_gemm<true,false,true>,   cudaFuncAttributeMaxDynamicSharedMemorySize, 98304);
    cudaFuncSetAttribute(flash_attn,                  cudaFuncAttributeMaxDynamicSharedMemorySize, 49152);

    wconv<<<1728, 256>>>(w_qkv,  wq,  768 * 2304);
    wconv<<<576,  256>>>(w_proj, wp,  768 * 768);
    wconv<<<2304, 256>>>(w1,     wf1, 768 * 3072);
    wconv<<<2304, 256>>>(w2,     wf2, 3072 * 768);

    ln_conv<<<NT, 256>>>(x, g1, beta1, hh);
    lin_gemm<false, false, true><<<dim3(18, 64), 256, 98304>>>(
        hh, DIM, wq, 3 * DIM, b_qkv, nullptr,
        nullptr, qk, 3 * DIM, DIM);
    flash_attn<<<dim3(16, NBH), 256, 49152>>>(qk, mask, at);
    lin_gemm<false, true, false><<<dim3(6, 64), 256, 98304>>>(
        at, DIM, wp, DIM, b_proj, x,
        x1, nullptr, DIM, DIM);
    ln_conv<<<NT, 256>>>(x1, g2, beta2, h2);
    lin_gemm<true, false, true><<<dim3(24, 64), 256, 98304>>>(
        h2, DIM, wf1, HID, b1, nullptr,
        nullptr, ac, HID, DIM);
    lin_gemm<false, true, false><<<dim3(6, 64), 256, 98304>>>(
        ac, HID, wf2, DIM, b2, x1,
        out, nullptr, DIM, HID);
}